// round 1
// baseline (speedup 1.0000x reference)
#include <cuda_runtime.h>
#include <math.h>

// Problem constants
#define BATCH   8
#define SEQ     4096
#define M_TOTAL (BATCH * SEQ)   // 32768
#define NCODES  1024
#define KDIM    256
#define TOPM    3
#define NEGVAL  -10000.0f

// GEMM tiling
#define BM 128
#define BN 128
#define BK 16

// ---------------------------------------------------------------------------
// Kernel 1: sim = q @ codes^T   (M=32768, N=1024, K=256), fp32
// Classic register-blocked SGEMM. Both operands are K-contiguous (NT layout).
// Smem tiles stored K-major (transposed) so fragment reads are LDS.128
// with conflict-free split-fragment addressing.
// ---------------------------------------------------------------------------
__global__ __launch_bounds__(256, 2)
void vq_sgemm_kernel(const float* __restrict__ A,    // [M_TOTAL, KDIM]
                     const float* __restrict__ Bm,   // [NCODES,  KDIM]
                     float* __restrict__ C)          // [M_TOTAL, NCODES]
{
    __shared__ float As[BK][BM + 4];   // stride 132 floats
    __shared__ float Bs[BK][BN + 4];

    const int bn0 = blockIdx.x * BN;
    const int bm0 = blockIdx.y * BM;
    const int tid = threadIdx.x;
    const int tx  = tid & 15;          // 0..15 -> N
    const int ty  = tid >> 4;          // 0..15 -> M

    float acc[8][8];
#pragma unroll
    for (int i = 0; i < 8; i++)
#pragma unroll
        for (int j = 0; j < 8; j++) acc[i][j] = 0.0f;

    for (int k0 = 0; k0 < KDIM; k0 += BK) {
        // Load A tile: 128 rows x 16 cols = 512 float4, 2 per thread.
#pragma unroll
        for (int i = 0; i < 2; i++) {
            int lin = tid + i * 256;
            int row = lin >> 2;
            int c4  = lin & 3;
            float4 v = *reinterpret_cast<const float4*>(
                &A[(size_t)(bm0 + row) * KDIM + k0 + c4 * 4]);
            As[c4 * 4 + 0][row] = v.x;
            As[c4 * 4 + 1][row] = v.y;
            As[c4 * 4 + 2][row] = v.z;
            As[c4 * 4 + 3][row] = v.w;
        }
        // Load B tile (codes): same pattern.
#pragma unroll
        for (int i = 0; i < 2; i++) {
            int lin = tid + i * 256;
            int row = lin >> 2;
            int c4  = lin & 3;
            float4 v = *reinterpret_cast<const float4*>(
                &Bm[(size_t)(bn0 + row) * KDIM + k0 + c4 * 4]);
            Bs[c4 * 4 + 0][row] = v.x;
            Bs[c4 * 4 + 1][row] = v.y;
            Bs[c4 * 4 + 2][row] = v.z;
            Bs[c4 * 4 + 3][row] = v.w;
        }
        __syncthreads();

#pragma unroll
        for (int kk = 0; kk < BK; kk++) {
            float a[8], b[8];
            *reinterpret_cast<float4*>(&a[0]) =
                *reinterpret_cast<const float4*>(&As[kk][ty * 4]);
            *reinterpret_cast<float4*>(&a[4]) =
                *reinterpret_cast<const float4*>(&As[kk][64 + ty * 4]);
            *reinterpret_cast<float4*>(&b[0]) =
                *reinterpret_cast<const float4*>(&Bs[kk][tx * 4]);
            *reinterpret_cast<float4*>(&b[4]) =
                *reinterpret_cast<const float4*>(&Bs[kk][64 + tx * 4]);
#pragma unroll
            for (int i = 0; i < 8; i++)
#pragma unroll
                for (int j = 0; j < 8; j++)
                    acc[i][j] = fmaf(a[i], b[j], acc[i][j]);
        }
        __syncthreads();
    }

    // Epilogue: split fragments -> rows {ty*4+ii, 64+ty*4+ii},
    //                              cols {tx*4+jj, 64+tx*4+jj}
#pragma unroll
    for (int ih = 0; ih < 2; ih++) {
#pragma unroll
        for (int ii = 0; ii < 4; ii++) {
            int row = bm0 + ih * 64 + ty * 4 + ii;
            float* crow = &C[(size_t)row * NCODES + bn0];
            float4 v0 = make_float4(acc[ih * 4 + ii][0], acc[ih * 4 + ii][1],
                                    acc[ih * 4 + ii][2], acc[ih * 4 + ii][3]);
            float4 v1 = make_float4(acc[ih * 4 + ii][4], acc[ih * 4 + ii][5],
                                    acc[ih * 4 + ii][6], acc[ih * 4 + ii][7]);
            *reinterpret_cast<float4*>(&crow[tx * 4])      = v0;
            *reinterpret_cast<float4*>(&crow[64 + tx * 4]) = v1;
        }
    }
}

// ---------------------------------------------------------------------------
// Kernel 2: per-row masked top-3 + Gumbel softmax. One warp per row.
// Tie-break: smaller code index wins (matches jax.lax.top_k).
// ---------------------------------------------------------------------------
__global__ __launch_bounds__(256)
void vq_topk_kernel(const float* __restrict__ sim,   // [M_TOTAL, NCODES]
                    const int*   __restrict__ mask,  // [M_TOTAL]
                    const float* __restrict__ u,     // [M_TOTAL, 3]
                    float* __restrict__ out_idx,     // [M_TOTAL, 3] (as float)
                    float* __restrict__ out_w)       // [M_TOTAL, 3]
{
    const int row  = blockIdx.x * 8 + (threadIdx.x >> 5);
    const int lane = threadIdx.x & 31;
    const float* srow = sim + (size_t)row * NCODES;

    const float NEG_INF = -__int_as_float(0x7f800000);  // -inf
    float v0 = NEG_INF, v1 = NEG_INF, v2 = NEG_INF;
    int   i0 = 0x7fffffff, i1 = 0x7fffffff, i2 = 0x7fffffff;

    // Each lane scans 32 values via 8 float4 loads; within-lane index order is
    // strictly increasing so strict '>' keeps the smaller index on ties.
#pragma unroll
    for (int t = 0; t < NCODES / 128; t++) {
        int base = t * 128 + lane * 4;
        float4 v4 = *reinterpret_cast<const float4*>(&srow[base]);
        float vv[4] = {v4.x, v4.y, v4.z, v4.w};
#pragma unroll
        for (int e = 0; e < 4; e++) {
            float v = vv[e];
            int idx = base + e;
            if (v > v0)      { v2 = v1; i2 = i1; v1 = v0; i1 = i0; v0 = v; i0 = idx; }
            else if (v > v1) { v2 = v1; i2 = i1; v1 = v;  i1 = idx; }
            else if (v > v2) { v2 = v;  i2 = idx; }
        }
    }

    // Warp merge: 3 rounds of (value, index) arg-max with smaller-index
    // tie-break. Each lane keeps a cursor into its sorted local top-3.
    float lv[3] = {v0, v1, v2};
    int   li[3] = {i0, i1, i2};
    float tv[3];
    int   ti[3];
    int p = 0;
#pragma unroll
    for (int r = 0; r < 3; r++) {
        float bv = (p < 3) ? lv[p] : NEG_INF;
        int   bi = (p < 3) ? li[p] : 0x7fffffff;
#pragma unroll
        for (int off = 16; off > 0; off >>= 1) {
            float ov = __shfl_xor_sync(0xffffffffu, bv, off);
            int   oi = __shfl_xor_sync(0xffffffffu, bi, off);
            if (ov > bv || (ov == bv && oi < bi)) { bv = ov; bi = oi; }
        }
        tv[r] = bv; ti[r] = bi;
        if (p < 3 && li[p] == bi) p++;   // winner lane advances its cursor
    }

    if (lane == 0) {
        int m = mask[row];
        if (m == 0) {
            // All sims masked to -10000 (equal): lax.top_k -> indices 0,1,2;
            // weights zeroed by the mask.
#pragma unroll
            for (int r = 0; r < 3; r++) {
                out_idx[row * 3 + r] = (float)r;
                out_w[row * 3 + r]   = 0.0f;
            }
        } else {
            float l[3];
#pragma unroll
            for (int r = 0; r < 3; r++) {
                float uu = u[row * 3 + r];
                uu = fminf(fmaxf(uu, 1e-7f), 1.0f - 1e-7f);
                float inner = fmaxf(-logf(uu), 1e-7f);
                float g = -logf(inner);
                l[r] = tv[r] + g;          // TAU = 1.0
            }
            float mx = fmaxf(l[0], fmaxf(l[1], l[2]));
            float e0 = expf(l[0] - mx);
            float e1 = expf(l[1] - mx);
            float e2 = expf(l[2] - mx);
            float inv = 1.0f / (e0 + e1 + e2);
#pragma unroll
            for (int r = 0; r < 3; r++) {
                out_idx[row * 3 + r] = (float)ti[r];
            }
            out_w[row * 3 + 0] = e0 * inv;
            out_w[row * 3 + 1] = e1 * inv;
            out_w[row * 3 + 2] = e2 * inv;
        }
    }
}

// ---------------------------------------------------------------------------
// Launch: d_out layout = [top_idx (B*N*3) | weights (B*N*3) | sim (B*N*K)]
// ---------------------------------------------------------------------------
extern "C" void kernel_launch(void* const* d_in, const int* in_sizes, int n_in,
                              void* d_out, int out_size)
{
    const float* q     = (const float*)d_in[0];   // [8,4096,256]
    const float* codes = (const float*)d_in[1];   // [1024,256]
    const int*   mask  = (const int*)  d_in[2];   // [8,4096]
    const float* u     = (const float*)d_in[3];   // [8,4096,3]

    float* out      = (float*)d_out;
    float* out_idx  = out;
    float* out_w    = out + (size_t)M_TOTAL * TOPM;
    float* sim      = out + (size_t)2 * M_TOTAL * TOPM;

    dim3 grid(NCODES / BN, M_TOTAL / BM);
    vq_sgemm_kernel<<<grid, 256>>>(q, codes, sim);

    vq_topk_kernel<<<M_TOTAL / 8, 256>>>(sim, mask, u, out_idx, out_w);
}

// round 4
// speedup vs baseline: 1.1082x; 1.1082x over previous
#include <cuda_runtime.h>
#include <math.h>

// Problem constants
#define BATCH   8
#define SEQ     4096
#define M_TOTAL (BATCH * SEQ)   // 32768
#define NCODES  1024
#define KDIM    256
#define TOPM    3

// GEMM tiling
#define BM 128
#define BN 128
#define BK 16

// ---------------------------------------------------------------------------
// Packed fp32x2 helpers (sm_100 Blackwell dual-lane FP32, bit-exact vs fmaf)
// ---------------------------------------------------------------------------
__device__ __forceinline__ unsigned long long pack2(float x) {
    unsigned long long r;
    asm("mov.b64 %0, {%1, %1};" : "=l"(r) : "f"(x));
    return r;
}
__device__ __forceinline__ void fma2(unsigned long long& acc,
                                     unsigned long long a,
                                     unsigned long long b) {
    asm("fma.rn.f32x2 %0, %1, %2, %0;" : "+l"(acc) : "l"(a), "l"(b));
}
__device__ __forceinline__ float2 unpack2(unsigned long long v) {
    float2 f;
    asm("mov.b64 {%0, %1}, %2;" : "=f"(f.x), "=f"(f.y) : "l"(v));
    return f;
}

// ---------------------------------------------------------------------------
// Kernel 1: sim = q @ codes^T   (M=32768, N=1024, K=256), fp32 via fma.f32x2
// Smem tiles stored K-major (transposed) so fragment reads are LDS.128.
// Register prefetch of next K-chunk overlaps LDG with compute.
// ---------------------------------------------------------------------------
__global__ __launch_bounds__(256, 2)
void vq_sgemm_kernel(const float* __restrict__ A,    // [M_TOTAL, KDIM]
                     const float* __restrict__ Bm,   // [NCODES,  KDIM]
                     float* __restrict__ C)          // [M_TOTAL, NCODES]
{
    __shared__ float As[BK][BM + 4];   // stride 132 floats (528 B, 16B-aligned)
    __shared__ float Bs[BK][BN + 4];

    const int bn0 = blockIdx.x * BN;
    const int bm0 = blockIdx.y * BM;
    const int tid = threadIdx.x;
    const int tx  = tid & 15;          // 0..15 -> N
    const int ty  = tid >> 4;          // 0..15 -> M

    // Per-thread load coordinates (2 float4 per operand per chunk)
    const int lrow0 = tid >> 2;              // 0..63
    const int lrow1 = lrow0 + 64;            // 64..127
    const int lc4   = (tid & 3) * 4;         // 0,4,8,12

    const float* Aptr0 = &A[(size_t)(bm0 + lrow0) * KDIM + lc4];
    const float* Aptr1 = &A[(size_t)(bm0 + lrow1) * KDIM + lc4];
    const float* Bptr0 = &Bm[(size_t)(bn0 + lrow0) * KDIM + lc4];
    const float* Bptr1 = &Bm[(size_t)(bn0 + lrow1) * KDIM + lc4];

    unsigned long long acc2[8][4];
#pragma unroll
    for (int i = 0; i < 8; i++)
#pragma unroll
        for (int j = 0; j < 4; j++) acc2[i][j] = 0ull;

    // Prologue: load chunk 0
    float4 pa0 = *reinterpret_cast<const float4*>(Aptr0);
    float4 pa1 = *reinterpret_cast<const float4*>(Aptr1);
    float4 pb0 = *reinterpret_cast<const float4*>(Bptr0);
    float4 pb1 = *reinterpret_cast<const float4*>(Bptr1);

#pragma unroll 1
    for (int c = 0; c < KDIM / BK; c++) {
        // Store prefetched chunk into transposed smem tiles
        As[lc4 + 0][lrow0] = pa0.x; As[lc4 + 1][lrow0] = pa0.y;
        As[lc4 + 2][lrow0] = pa0.z; As[lc4 + 3][lrow0] = pa0.w;
        As[lc4 + 0][lrow1] = pa1.x; As[lc4 + 1][lrow1] = pa1.y;
        As[lc4 + 2][lrow1] = pa1.z; As[lc4 + 3][lrow1] = pa1.w;
        Bs[lc4 + 0][lrow0] = pb0.x; Bs[lc4 + 1][lrow0] = pb0.y;
        Bs[lc4 + 2][lrow0] = pb0.z; Bs[lc4 + 3][lrow0] = pb0.w;
        Bs[lc4 + 0][lrow1] = pb1.x; Bs[lc4 + 1][lrow1] = pb1.y;
        Bs[lc4 + 2][lrow1] = pb1.z; Bs[lc4 + 3][lrow1] = pb1.w;
        __syncthreads();

        // Issue next chunk's global loads before compute (latency hiding)
        if (c + 1 < KDIM / BK) {
            int koff = (c + 1) * BK;
            pa0 = *reinterpret_cast<const float4*>(Aptr0 + koff);
            pa1 = *reinterpret_cast<const float4*>(Aptr1 + koff);
            pb0 = *reinterpret_cast<const float4*>(Bptr0 + koff);
            pb1 = *reinterpret_cast<const float4*>(Bptr1 + koff);
        }

#pragma unroll
        for (int kk = 0; kk < BK; kk++) {
            float4 a0 = *reinterpret_cast<const float4*>(&As[kk][ty * 4]);
            float4 a1 = *reinterpret_cast<const float4*>(&As[kk][64 + ty * 4]);
            ulonglong2 bp = *reinterpret_cast<const ulonglong2*>(&Bs[kk][tx * 4]);
            ulonglong2 bq = *reinterpret_cast<const ulonglong2*>(&Bs[kk][64 + tx * 4]);

            float av[8] = {a0.x, a0.y, a0.z, a0.w, a1.x, a1.y, a1.z, a1.w};
#pragma unroll
            for (int i = 0; i < 8; i++) {
                unsigned long long ap = pack2(av[i]);
                fma2(acc2[i][0], ap, bp.x);
                fma2(acc2[i][1], ap, bp.y);
                fma2(acc2[i][2], ap, bq.x);
                fma2(acc2[i][3], ap, bq.y);
            }
        }
        __syncthreads();
    }

    // Epilogue: rows {ty*4+ii, 64+ty*4+ii}, cols {tx*4.., 64+tx*4..}
#pragma unroll
    for (int ih = 0; ih < 2; ih++) {
#pragma unroll
        for (int ii = 0; ii < 4; ii++) {
            int i = ih * 4 + ii;
            int row = bm0 + ih * 64 + ty * 4 + ii;
            float* crow = &C[(size_t)row * NCODES + bn0];
            float2 c0 = unpack2(acc2[i][0]);
            float2 c1 = unpack2(acc2[i][1]);
            float2 c2 = unpack2(acc2[i][2]);
            float2 c3 = unpack2(acc2[i][3]);
            *reinterpret_cast<float4*>(&crow[tx * 4]) =
                make_float4(c0.x, c0.y, c1.x, c1.y);
            *reinterpret_cast<float4*>(&crow[64 + tx * 4]) =
                make_float4(c2.x, c2.y, c3.x, c3.y);
        }
    }
}

// ---------------------------------------------------------------------------
// Kernel 2: per-row masked top-3 + Gumbel softmax. One warp per row.
// Tie-break: smaller code index wins (matches jax.lax.top_k).
// ---------------------------------------------------------------------------
__global__ __launch_bounds__(256)
void vq_topk_kernel(const float* __restrict__ sim,   // [M_TOTAL, NCODES]
                    const int*   __restrict__ mask,  // [M_TOTAL]
                    const float* __restrict__ u,     // [M_TOTAL, 3]
                    float* __restrict__ out_idx,     // [M_TOTAL, 3] (as float)
                    float* __restrict__ out_w)       // [M_TOTAL, 3]
{
    const int row  = blockIdx.x * 8 + (threadIdx.x >> 5);
    const int lane = threadIdx.x & 31;
    const float* srow = sim + (size_t)row * NCODES;

    const float NEG_INF = -__int_as_float(0x7f800000);  // -inf
    float v0 = NEG_INF, v1 = NEG_INF, v2 = NEG_INF;
    int   i0 = 0x7fffffff, i1 = 0x7fffffff, i2 = 0x7fffffff;

#pragma unroll
    for (int t = 0; t < NCODES / 128; t++) {
        int base = t * 128 + lane * 4;
        float4 v4 = *reinterpret_cast<const float4*>(&srow[base]);
        float vv[4] = {v4.x, v4.y, v4.z, v4.w};
#pragma unroll
        for (int e = 0; e < 4; e++) {
            float v = vv[e];
            int idx = base + e;
            if (v > v0)      { v2 = v1; i2 = i1; v1 = v0; i1 = i0; v0 = v; i0 = idx; }
            else if (v > v1) { v2 = v1; i2 = i1; v1 = v;  i1 = idx; }
            else if (v > v2) { v2 = v;  i2 = idx; }
        }
    }

    // Warp merge: 3 rounds of (value, index) arg-max with smaller-index
    // tie-break. Each lane keeps a cursor into its sorted local top-3.
    float lv[3] = {v0, v1, v2};
    int   li[3] = {i0, i1, i2};
    float tv[3];
    int   ti[3];
    int p = 0;
#pragma unroll
    for (int r = 0; r < 3; r++) {
        float bv = (p < 3) ? lv[p] : NEG_INF;
        int   bi = (p < 3) ? li[p] : 0x7fffffff;
#pragma unroll
        for (int off = 16; off > 0; off >>= 1) {
            float ov = __shfl_xor_sync(0xffffffffu, bv, off);
            int   oi = __shfl_xor_sync(0xffffffffu, bi, off);
            if (ov > bv || (ov == bv && oi < bi)) { bv = ov; bi = oi; }
        }
        tv[r] = bv; ti[r] = bi;
        if (p < 3 && li[p] == bi) p++;   // winner lane advances its cursor
    }

    if (lane == 0) {
        int m = mask[row];
        if (m == 0) {
            // All sims masked to -10000 (equal): lax.top_k -> indices 0,1,2;
            // weights zeroed by the mask.
#pragma unroll
            for (int r = 0; r < 3; r++) {
                out_idx[row * 3 + r] = (float)r;
                out_w[row * 3 + r]   = 0.0f;
            }
        } else {
            float l[3];
#pragma unroll
            for (int r = 0; r < 3; r++) {
                float uu = u[row * 3 + r];
                uu = fminf(fmaxf(uu, 1e-7f), 1.0f - 1e-7f);
                float inner = fmaxf(-logf(uu), 1e-7f);
                float g = -logf(inner);
                l[r] = tv[r] + g;          // TAU = 1.0
            }
            float mx = fmaxf(l[0], fmaxf(l[1], l[2]));
            float e0 = expf(l[0] - mx);
            float e1 = expf(l[1] - mx);
            float e2 = expf(l[2] - mx);
            float inv = 1.0f / (e0 + e1 + e2);
#pragma unroll
            for (int r = 0; r < 3; r++) {
                out_idx[row * 3 + r] = (float)ti[r];
            }
            out_w[row * 3 + 0] = e0 * inv;
            out_w[row * 3 + 1] = e1 * inv;
            out_w[row * 3 + 2] = e2 * inv;
        }
    }
}

// ---------------------------------------------------------------------------
// Launch: d_out layout = [top_idx (B*N*3) | weights (B*N*3) | sim (B*N*K)]
// ---------------------------------------------------------------------------
extern "C" void kernel_launch(void* const* d_in, const int* in_sizes, int n_in,
                              void* d_out, int out_size)
{
    const float* q     = (const float*)d_in[0];   // [8,4096,256]
    const float* codes = (const float*)d_in[1];   // [1024,256]
    const int*   mask  = (const int*)  d_in[2];   // [8,4096]
    const float* u     = (const float*)d_in[3];   // [8,4096,3]

    float* out      = (float*)d_out;
    float* out_idx  = out;
    float* out_w    = out + (size_t)M_TOTAL * TOPM;
    float* sim      = out + (size_t)2 * M_TOTAL * TOPM;

    dim3 grid(NCODES / BN, M_TOTAL / BM);
    vq_sgemm_kernel<<<grid, 256>>>(q, codes, sim);

    vq_topk_kernel<<<M_TOTAL / 8, 256>>>(sim, mask, u, out_idx, out_w);
}